// round 12
// baseline (speedup 1.0000x reference)
#include <cuda_runtime.h>
#include <cuda_bf16.h>

// text [SEQ=200, BATCH=4096] int32 (row-major text[s*BATCH+b]),
// w [V=50000] f32, bias [1] f32.  out[b] = sum_{unique t in doc b} w[t] + bias.
//
// R12: SELF-VALIDATING markers -> no table init, 3 syncs (was 6 in R9).
// Marker slots hold a claimed seq index m (u8, may be garbage/stale). A read
// accepts m only if m<SEQ && toks[doc][m]==t; then m is provably in the same
// token group, so "thread m contributes" is exactly-once whether or not m
// actually stored. All same-token threads read the same slot -> same verdict.
// Therefore: L1 stores merge into the load phase (no init to order against),
// and unresolved items store L2+L3 tables simultaneously (disjoint). Exact
// scan fallback reached by ~9% of blocks (one warp, ~3K cyc).
// Shape = R9: DOCS=4, NTHR=256, grid 1024, speculative gathers.

#define SEQ    200
#define BATCH  4096
#define DOCS   4
#define NTHR   256
#define NITEM  (SEQ * DOCS)       // 800
#define ABITS  11
#define BBITS  9
#define CBITS  9
#define ASZ    (1 << ABITS)       // 2048 u8 slots/doc
#define BSZ    (1 << BBITS)       // 512
#define CSZ    (1 << CBITS)       // 512

__global__ __launch_bounds__(NTHR, 8)
void MNB_24111946400019_kernel(const int* __restrict__ text,
                               const float* __restrict__ w,
                               const float* __restrict__ bias,
                               float* __restrict__ out)
{
    __shared__ int           toks[DOCS * SEQ];     // 3.2KB
    __shared__ unsigned char tabA[DOCS * ASZ];     // 8KB  (UNINITIALIZED)
    __shared__ unsigned char tabB[DOCS * BSZ];     // 2KB  (UNINITIALIZED)
    __shared__ unsigned char tabC[DOCS * CSZ];     // 2KB  (UNINITIALIZED)
    __shared__ float         part[DOCS][9];

    const int b0  = blockIdx.x * DOCS;
    const int tid = threadIdx.x;
    const int d   = tid & 3;                 // this thread's doc (256%4==0)
    const int dt  = d * SEQ;

    int      tt[4];
    float    wv[4];
    unsigned hh[4];
    int      st[4];

    // ── Phase 0: text load (coalesced, i=s*4+d), speculative gathers,
    //    toks store, AND level-1 marker store (no init needed). ──
    #pragma unroll
    for (int k = 0; k < 4; ++k) {
        const int i = tid + k * NTHR;
        tt[k] = (i < NITEM) ? __ldg(&text[(i >> 2) * BATCH + b0 + d]) : 0;
    }
    #pragma unroll
    for (int k = 0; k < 4; ++k) wv[k] = __ldg(&w[tt[k]]);     // latency hides below
    #pragma unroll
    for (int k = 0; k < 4; ++k) {
        const int i = tid + k * NTHR;
        const int s = i >> 2;
        hh[k] = ((unsigned)tt[k] * 2654435761u) >> (32 - ABITS);
        if (i < NITEM) {
            toks[dt + s] = tt[k];
            tabA[d * ASZ + hh[k]] = (unsigned char)s;
        }
    }
    __syncthreads();

    // ── Phase 1: read A (verified), unresolved store B and C simultaneously ──
    #pragma unroll
    for (int k = 0; k < 4; ++k) {
        st[k] = 0;
        const int i = tid + k * NTHR;
        if (i < NITEM) {
            const int s = i >> 2;
            const int m = tabA[d * ASZ + hh[k]];
            if (m < SEQ && toks[dt + m] == tt[k]) {
                st[k] = (m == s) ? 1 : 0;          // verified claimant wins
            } else {
                st[k] = 2;                          // ~19/doc
                const unsigned hb = ((unsigned)tt[k] * 0x85EBCA77u) >> (32 - BBITS);
                const unsigned hc = ((unsigned)tt[k] * 0xC2B2AE3Du) >> (32 - CBITS);
                tabB[d * BSZ + hb] = (unsigned char)s;
                tabC[d * CSZ + hc] = (unsigned char)s;
            }
        }
    }
    __syncthreads();

    // ── Phase 2: resolve via B, then C, then exact scan; accumulate ──
    float v = 0.0f;
    #pragma unroll
    for (int k = 0; k < 4; ++k) {
        int c = st[k];
        if (c == 2) {
            const int s  = (tid + k * NTHR) >> 2;
            const unsigned hb = ((unsigned)tt[k] * 0x85EBCA77u) >> (32 - BBITS);
            int m = tabB[d * BSZ + hb];
            if (m < SEQ && toks[dt + m] == tt[k]) {
                c = (m == s) ? 1 : 0;
            } else {
                const unsigned hc = ((unsigned)tt[k] * 0xC2B2AE3Du) >> (32 - CBITS);
                m = tabC[d * CSZ + hc];
                if (m < SEQ && toks[dt + m] == tt[k]) {
                    c = (m == s) ? 1 : 0;
                } else {
                    // Exact first-occurrence scan (~9% of blocks, one item).
                    int f = 0;
                    while (toks[dt + f] != tt[k]) ++f;   // terminates at f==s
                    c = (f == s) ? 1 : 0;
                }
            }
        }
        if (c == 1) v += wv[k];
    }

    // ── Per-doc reduction: lanes with equal (lane&3) share a doc ──
    v += __shfl_xor_sync(0xffffffffu, v, 16);
    v += __shfl_xor_sync(0xffffffffu, v, 8);
    v += __shfl_xor_sync(0xffffffffu, v, 4);
    if ((tid & 31) < 4) part[d][tid >> 5] = v;           // 8 warps
    __syncthreads();

    if (tid < 32) {
        const int dd = tid >> 3;                         // doc 0..3
        const int j  = tid & 7;                          // warp slot
        float s = part[dd][j];
        s += __shfl_xor_sync(0xffffffffu, s, 4);
        s += __shfl_xor_sync(0xffffffffu, s, 2);
        s += __shfl_xor_sync(0xffffffffu, s, 1);
        if (j == 0) out[b0 + dd] = s + bias[0];
    }
}

extern "C" void kernel_launch(void* const* d_in, const int* in_sizes, int n_in,
                              void* d_out, int out_size)
{
    const int*   text = (const int*)d_in[0];
    const float* w    = (const float*)d_in[1];
    const float* bias = (const float*)d_in[2];
    float*       out  = (float*)d_out;

    MNB_24111946400019_kernel<<<BATCH / DOCS, NTHR>>>(text, w, bias, out);
}

// round 13
// speedup vs baseline: 1.0312x; 1.0312x over previous
#include <cuda_runtime.h>
#include <cuda_bf16.h>

// text [SEQ=200, BATCH=4096] int32 (row-major text[s*BATCH+b]),
// w [V=50000] f32, bias [1] f32.  out[b] = sum_{unique t in doc b} w[t] + bias.
//
// R13 = R9 (best: 8.54us kernel) with ONE structural delta, keeping the
// phase-0 marker init (R12 proved it is the latency filler for the text LDG,
// not waste): levels 2 and 3 merge into a single phase using DISJOINT
// uninitialized tables B and C — unresolved items store both at once, then
// read them back next phase. Each unresolved thread reads slots it stored in
// the same phase, so the content is always a genuine same-phase racer
// (no init needed, no stale-read hazard). Exact scan reached ~0.3% of blocks.
// Syncs: 6 -> 5.  Shape: DOCS=4, NTHR=256, grid=1024, speculative gathers.

#define SEQ    200
#define BATCH  4096
#define DOCS   4
#define NTHR   256
#define NITEM  (SEQ * DOCS)       // 800
#define ABITS  11
#define BBITS  9
#define CBITS  9
#define ASZ    (1 << ABITS)       // 2048 u8 slots/doc
#define BSZ    (1 << BBITS)       // 512 (uninitialized)
#define CSZ    (1 << CBITS)       // 512 (uninitialized)

__global__ __launch_bounds__(NTHR, 8)
void MNB_24111946400019_kernel(const int* __restrict__ text,
                               const float* __restrict__ w,
                               const float* __restrict__ bias,
                               float* __restrict__ out)
{
    __shared__ int           toks[DOCS * SEQ];     // 3.2KB
    __shared__ unsigned char tabA[DOCS * ASZ];     // 8KB (initialized: filler)
    __shared__ unsigned char tabB[DOCS * BSZ];     // 2KB (uninitialized)
    __shared__ unsigned char tabC[DOCS * CSZ];     // 2KB (uninitialized)
    __shared__ float         part[DOCS][9];

    const int b0  = blockIdx.x * DOCS;
    const int tid = threadIdx.x;
    const int d   = tid & 3;                 // this thread's doc (256%4==0)
    const int dt  = d * SEQ;
    const int dm  = d * ASZ;

    int      tt[4];
    float    wv[4];
    unsigned hh[4];
    int      st[4];

    // ── Phase 0: text load (coalesced, i=s*4+d) + speculative gathers,
    //    overlapped by the A-table init (independent ALU/STS filler). ──
    #pragma unroll
    for (int k = 0; k < 4; ++k) {
        const int i = tid + k * NTHR;
        tt[k] = (i < NITEM) ? __ldg(&text[(i >> 2) * BATCH + b0 + d]) : 0;
    }
    #pragma unroll
    for (int k = 0; k < 4; ++k) wv[k] = __ldg(&w[tt[k]]);     // in flight
    {
        int4* a4 = reinterpret_cast<int4*>(tabA);
        const int4 ff = make_int4(-1, -1, -1, -1);
        a4[tid]        = ff;                                   // 8KB filler
        a4[tid + NTHR] = ff;
    }
    #pragma unroll
    for (int k = 0; k < 4; ++k) {
        const int i = tid + k * NTHR;
        if (i < NITEM) toks[dt + (i >> 2)] = tt[k];
    }
    __syncthreads();

    // ── Phase 1: level-1 racing byte store ──
    #pragma unroll
    for (int k = 0; k < 4; ++k) {
        const int i = tid + k * NTHR;
        hh[k] = ((unsigned)tt[k] * 2654435761u) >> (32 - ABITS);
        if (i < NITEM) tabA[dm + hh[k]] = (unsigned char)(i >> 2);
    }
    __syncthreads();

    // ── Phase 2: read A; unresolved store B AND C (disjoint) at once ──
    #pragma unroll
    for (int k = 0; k < 4; ++k) {
        st[k] = 0;
        const int i = tid + k * NTHR;
        if (i < NITEM) {
            const int s = i >> 2;
            const int m = tabA[dm + hh[k]];        // genuine same-phase racer
            if (toks[dt + m] == tt[k]) {
                st[k] = (m == s) ? 1 : 0;          // winner / duplicate
            } else {
                st[k] = 2;                          // ~19/doc
                const unsigned hb = ((unsigned)tt[k] * 0x85EBCA77u) >> (32 - BBITS);
                const unsigned hc = ((unsigned)tt[k] * 0xC2B2AE3Du) >> (32 - CBITS);
                tabB[d * BSZ + hb] = (unsigned char)s;
                tabC[d * CSZ + hc] = (unsigned char)s;
                hh[k] = hb;                         // keep hb; recompute hc later
            }
        }
    }
    __syncthreads();

    // ── Phase 3: resolve B -> C -> exact scan; accumulate ──
    float v = 0.0f;
    #pragma unroll
    for (int k = 0; k < 4; ++k) {
        int c = st[k];
        if (c == 2) {
            const int s = (tid + k * NTHR) >> 2;
            int m = tabB[d * BSZ + hh[k]];          // stored this slot ourselves
            if (toks[dt + m] == tt[k]) {
                c = (m == s) ? 1 : 0;
            } else {
                const unsigned hc = ((unsigned)tt[k] * 0xC2B2AE3Du) >> (32 - CBITS);
                m = tabC[d * CSZ + hc];             // ditto
                if (toks[dt + m] == tt[k]) {
                    c = (m == s) ? 1 : 0;
                } else {
                    // Exact first-occurrence scan (~0.3% of blocks, one item).
                    int f = 0;
                    while (toks[dt + f] != tt[k]) ++f;   // terminates at f==s
                    c = (f == s) ? 1 : 0;
                }
            }
        }
        if (c == 1) v += wv[k];
    }

    // ── Per-doc reduction: lanes with equal (lane&3) share a doc ──
    v += __shfl_xor_sync(0xffffffffu, v, 16);
    v += __shfl_xor_sync(0xffffffffu, v, 8);
    v += __shfl_xor_sync(0xffffffffu, v, 4);
    if ((tid & 31) < 4) part[d][tid >> 5] = v;           // 8 warps
    __syncthreads();

    if (tid < 32) {
        const int dd = tid >> 3;                         // doc 0..3
        const int j  = tid & 7;                          // warp slot
        float s = part[dd][j];
        s += __shfl_xor_sync(0xffffffffu, s, 4);
        s += __shfl_xor_sync(0xffffffffu, s, 2);
        s += __shfl_xor_sync(0xffffffffu, s, 1);
        if (j == 0) out[b0 + dd] = s + bias[0];
    }
}

extern "C" void kernel_launch(void* const* d_in, const int* in_sizes, int n_in,
                              void* d_out, int out_size)
{
    const int*   text = (const int*)d_in[0];
    const float* w    = (const float*)d_in[1];
    const float* bias = (const float*)d_in[2];
    float*       out  = (float*)d_out;

    MNB_24111946400019_kernel<<<BATCH / DOCS, NTHR>>>(text, w, bias, out);
}